// round 3
// baseline (speedup 1.0000x reference)
#include <cuda_runtime.h>

// Problem constants (fixed by the reference: B=32, M=4, D=196608)
constexpr int B_    = 32;
constexpr int M_    = 4;
constexpr int D_    = 196608;
constexpr int D4_   = D_ / 4;      // 49152 float4 per row
constexpr int BPG   = 9;           // blocks per group -> 288 blocks ~ 1 wave on 148 SMs
constexpr int TPB   = 256;
constexpr int NWARP = TPB / 32;
constexpr int NSLOT = 36;          // 10 (st gram uptri) + 10 (sr gram uptri) + 16 (cross)

// Static scratch: fixed-order two-pass reduction (deterministic, no atomics, no allocation)
__device__ float g_partials[B_ * BPG * NSLOT];

__global__ __launch_bounds__(TPB) void mmd_main(const float* __restrict__ st,
                                                const float* __restrict__ sr) {
    const int blk = blockIdx.x;
    const int b   = blk / BPG;
    const int sub = blk - b * BPG;

    // Row base pointers (float4 view). Row i of group b starts at (b*4+i)*D.
    const float4* __restrict__ A0 = reinterpret_cast<const float4*>(st) + (size_t)(b * M_ + 0) * D4_;
    const float4* __restrict__ A1 = reinterpret_cast<const float4*>(st) + (size_t)(b * M_ + 1) * D4_;
    const float4* __restrict__ A2 = reinterpret_cast<const float4*>(st) + (size_t)(b * M_ + 2) * D4_;
    const float4* __restrict__ A3 = reinterpret_cast<const float4*>(st) + (size_t)(b * M_ + 3) * D4_;
    const float4* __restrict__ C0 = reinterpret_cast<const float4*>(sr) + (size_t)(b * M_ + 0) * D4_;
    const float4* __restrict__ C1 = reinterpret_cast<const float4*>(sr) + (size_t)(b * M_ + 1) * D4_;
    const float4* __restrict__ C2 = reinterpret_cast<const float4*>(sr) + (size_t)(b * M_ + 2) * D4_;
    const float4* __restrict__ C3 = reinterpret_cast<const float4*>(sr) + (size_t)(b * M_ + 3) * D4_;

    float acc[NSLOT];
#pragma unroll
    for (int s = 0; s < NSLOT; s++) acc[s] = 0.0f;

    for (int k = sub * TPB + threadIdx.x; k < D4_; k += BPG * TPB) {
        // 8 independent 128-bit loads -> high MLP, fully coalesced per warp
        float4 a[4];
        float4 c[4];
        a[0] = A0[k]; a[1] = A1[k]; a[2] = A2[k]; a[3] = A3[k];
        c[0] = C0[k]; c[1] = C1[k]; c[2] = C2[k]; c[3] = C3[k];

#pragma unroll
        for (int v = 0; v < 4; v++) {
            float x[4], y[4];
#pragma unroll
            for (int i = 0; i < 4; i++) {
                x[i] = reinterpret_cast<const float*>(&a[i])[v];
                y[i] = reinterpret_cast<const float*>(&c[i])[v];
            }
            int s = 0;
#pragma unroll
            for (int i = 0; i < 4; i++)
#pragma unroll
                for (int j = i; j < 4; j++) { acc[s] = fmaf(x[i], x[j], acc[s]); s++; }
#pragma unroll
            for (int i = 0; i < 4; i++)
#pragma unroll
                for (int j = i; j < 4; j++) { acc[s] = fmaf(y[i], y[j], acc[s]); s++; }
#pragma unroll
            for (int i = 0; i < 4; i++)
#pragma unroll
                for (int j = 0; j < 4; j++) { acc[s] = fmaf(x[i], y[j], acc[s]); s++; }
        }
    }

    // Warp-level tree reduction of all 36 accumulators
#pragma unroll
    for (int s = 0; s < NSLOT; s++) {
        float v = acc[s];
        v += __shfl_down_sync(0xffffffffu, v, 16);
        v += __shfl_down_sync(0xffffffffu, v, 8);
        v += __shfl_down_sync(0xffffffffu, v, 4);
        v += __shfl_down_sync(0xffffffffu, v, 2);
        v += __shfl_down_sync(0xffffffffu, v, 1);
        acc[s] = v;
    }

    __shared__ float sm[NWARP][NSLOT];
    const int warp = threadIdx.x >> 5;
    const int lane = threadIdx.x & 31;
    if (lane == 0) {
#pragma unroll
        for (int s = 0; s < NSLOT; s++) sm[warp][s] = acc[s];
    }
    __syncthreads();

    if (threadIdx.x < NSLOT) {
        float t = 0.0f;
#pragma unroll
        for (int w = 0; w < NWARP; w++) t += sm[w][threadIdx.x];
        g_partials[blk * NSLOT + threadIdx.x] = t;
    }
}

__device__ __forceinline__ float kmean(const float (&GA)[4][4],
                                       const float (&GB)[4][4],
                                       const float (&XY)[4][4],
                                       float w) {
    const float invD = 1.0f / (float)D_;   // sigma = 1
    float sum = 0.0f;
#pragma unroll
    for (int i = 0; i < 4; i++) {
#pragma unroll
        for (int j = 0; j < 4; j++) {
            float d2 = GA[i][i] + GB[j][j] - 2.0f * XY[i][j];
            d2 = fmaxf(d2, 1e-12f);
            float dist = sqrtf(d2) * invD;
            float e = -dist * w;
            e = fminf(fmaxf(e, -1e6f), 0.0f);
            sum += expf(e);
        }
    }
    return sum * (1.0f / 16.0f);
}

__global__ __launch_bounds__(1024) void mmd_finalize(const float* __restrict__ wt,
                                                     const float* __restrict__ wtout,
                                                     float* __restrict__ out) {
    __shared__ float G[B_][NSLOT];
    __shared__ float lossS[B_];

    const int b    = threadIdx.x >> 5;   // warp b handles group b (32 warps)
    const int lane = threadIdx.x & 31;

    // Fixed-order sum over the BPG partial blocks of this group
    for (int s = lane; s < NSLOT; s += 32) {
        float t = 0.0f;
#pragma unroll
        for (int k = 0; k < BPG; k++) t += g_partials[(b * BPG + k) * NSLOT + s];
        G[b][s] = t;
    }
    __syncthreads();

    if (lane == 0) {
        float Gst[4][4], Gsr[4][4], C[4][4];
        int s = 0;
#pragma unroll
        for (int i = 0; i < 4; i++)
#pragma unroll
            for (int j = i; j < 4; j++) { Gst[i][j] = G[b][s]; Gst[j][i] = G[b][s]; s++; }
#pragma unroll
        for (int i = 0; i < 4; i++)
#pragma unroll
            for (int j = i; j < 4; j++) { Gsr[i][j] = G[b][s]; Gsr[j][i] = G[b][s]; s++; }
#pragma unroll
        for (int i = 0; i < 4; i++)
#pragma unroll
            for (int j = 0; j < 4; j++) { C[i][j] = G[b][s]; s++; }

        const float w = wt[b];
        float m1 = kmean(Gst, Gst, Gst, w);
        float m2 = kmean(Gsr, Gsr, Gsr, w);
        float m3 = kmean(Gst, Gsr, C, w);
        lossS[b] = wtout[b] * (m1 + m2 - 2.0f * m3);
    }
    __syncthreads();

    if (threadIdx.x == 0) {
        float t = 0.0f;
#pragma unroll
        for (int g = 0; g < B_; g++) t += lossS[g];
        out[0] = t * (1.0f / (float)B_);
    }
}

extern "C" void kernel_launch(void* const* d_in, const int* in_sizes, int n_in,
                              void* d_out, int out_size) {
    const float* f_st  = (const float*)d_in[0];
    const float* f_sr  = (const float*)d_in[1];
    const float* wt    = (const float*)d_in[2];
    const float* wtout = (const float*)d_in[3];
    float* out = (float*)d_out;

    mmd_main<<<B_ * BPG, TPB>>>(f_st, f_sr);
    mmd_finalize<<<1, 1024>>>(wt, wtout, out);
}

// round 4
// speedup vs baseline: 1.0320x; 1.0320x over previous
#include <cuda_runtime.h>

// Problem constants (fixed by the reference: B=32, M=4, D=196608)
constexpr int B_    = 32;
constexpr int M_    = 4;
constexpr int D_    = 196608;
constexpr int D4_   = D_ / 4;      // 49152 float4 per row
constexpr int BPG   = 9;           // blocks per group -> 288 blocks ~ 1 wave on 148 SMs
constexpr int TPB   = 256;
constexpr int NWARP = TPB / 32;
constexpr int NSLOT = 36;          // 10 (st gram uptri) + 10 (sr gram uptri) + 16 (cross)
constexpr int GRID  = B_ * BPG;

// Static scratch: fixed-order two-pass reduction (deterministic, no float atomics)
__device__ float        g_partials[GRID * NSLOT];
__device__ unsigned int g_counter = 0;   // blocks-done counter; reset by finalizing block

__device__ __forceinline__ float kmean4(const float (&GA)[4][4],
                                        const float (&GB)[4][4],
                                        const float (&XY)[4][4],
                                        float w) {
    const float invD = 1.0f / (float)D_;   // sigma = 1
    float sum = 0.0f;
#pragma unroll
    for (int i = 0; i < 4; i++) {
#pragma unroll
        for (int j = 0; j < 4; j++) {
            float d2 = GA[i][i] + GB[j][j] - 2.0f * XY[i][j];
            d2 = fmaxf(d2, 1e-12f);
            float dist = sqrtf(d2) * invD;
            float e = -dist * w;
            e = fminf(fmaxf(e, -1e6f), 0.0f);
            sum += expf(e);
        }
    }
    return sum * (1.0f / 16.0f);
}

__global__ __launch_bounds__(TPB) void mmd_fused(const float* __restrict__ st,
                                                 const float* __restrict__ sr,
                                                 const float* __restrict__ wt,
                                                 const float* __restrict__ wtout,
                                                 float* __restrict__ out) {
    const int blk = blockIdx.x;
    const int b   = blk / BPG;
    const int sub = blk - b * BPG;

    const float4* __restrict__ A0 = reinterpret_cast<const float4*>(st) + (size_t)(b * M_ + 0) * D4_;
    const float4* __restrict__ A1 = reinterpret_cast<const float4*>(st) + (size_t)(b * M_ + 1) * D4_;
    const float4* __restrict__ A2 = reinterpret_cast<const float4*>(st) + (size_t)(b * M_ + 2) * D4_;
    const float4* __restrict__ A3 = reinterpret_cast<const float4*>(st) + (size_t)(b * M_ + 3) * D4_;
    const float4* __restrict__ C0 = reinterpret_cast<const float4*>(sr) + (size_t)(b * M_ + 0) * D4_;
    const float4* __restrict__ C1 = reinterpret_cast<const float4*>(sr) + (size_t)(b * M_ + 1) * D4_;
    const float4* __restrict__ C2 = reinterpret_cast<const float4*>(sr) + (size_t)(b * M_ + 2) * D4_;
    const float4* __restrict__ C3 = reinterpret_cast<const float4*>(sr) + (size_t)(b * M_ + 3) * D4_;

    float acc[NSLOT];
#pragma unroll
    for (int s = 0; s < NSLOT; s++) acc[s] = 0.0f;

#pragma unroll 2
    for (int k = sub * TPB + threadIdx.x; k < D4_; k += BPG * TPB) {
        // 8 independent 128-bit loads per iter (x2 with unroll) -> deep MLP, coalesced
        float4 a[4];
        float4 c[4];
        a[0] = A0[k]; a[1] = A1[k]; a[2] = A2[k]; a[3] = A3[k];
        c[0] = C0[k]; c[1] = C1[k]; c[2] = C2[k]; c[3] = C3[k];

#pragma unroll
        for (int v = 0; v < 4; v++) {
            float x[4], y[4];
#pragma unroll
            for (int i = 0; i < 4; i++) {
                x[i] = reinterpret_cast<const float*>(&a[i])[v];
                y[i] = reinterpret_cast<const float*>(&c[i])[v];
            }
            int s = 0;
#pragma unroll
            for (int i = 0; i < 4; i++)
#pragma unroll
                for (int j = i; j < 4; j++) { acc[s] = fmaf(x[i], x[j], acc[s]); s++; }
#pragma unroll
            for (int i = 0; i < 4; i++)
#pragma unroll
                for (int j = i; j < 4; j++) { acc[s] = fmaf(y[i], y[j], acc[s]); s++; }
#pragma unroll
            for (int i = 0; i < 4; i++)
#pragma unroll
                for (int j = 0; j < 4; j++) { acc[s] = fmaf(x[i], y[j], acc[s]); s++; }
        }
    }

    // Warp tree reduction of all 36 accumulators
#pragma unroll
    for (int s = 0; s < NSLOT; s++) {
        float v = acc[s];
        v += __shfl_down_sync(0xffffffffu, v, 16);
        v += __shfl_down_sync(0xffffffffu, v, 8);
        v += __shfl_down_sync(0xffffffffu, v, 4);
        v += __shfl_down_sync(0xffffffffu, v, 2);
        v += __shfl_down_sync(0xffffffffu, v, 1);
        acc[s] = v;
    }

    __shared__ float sm[NWARP][NSLOT];
    const int warp = threadIdx.x >> 5;
    const int lane = threadIdx.x & 31;
    if (lane == 0) {
#pragma unroll
        for (int s = 0; s < NSLOT; s++) sm[warp][s] = acc[s];
    }
    __syncthreads();

    if (threadIdx.x < NSLOT) {
        float t = 0.0f;
#pragma unroll
        for (int w = 0; w < NWARP; w++) t += sm[w][threadIdx.x];
        g_partials[blk * NSLOT + threadIdx.x] = t;
    }

    // ---- last-block-done election ----
    __shared__ unsigned int s_isLast;
    __threadfence();                       // make partials visible before counting
    __syncthreads();                       // ensure this block's store happened
    if (threadIdx.x == 0) {
        unsigned int old = atomicAdd(&g_counter, 1u);
        s_isLast = (old == (unsigned int)(GRID - 1)) ? 1u : 0u;
    }
    __syncthreads();
    if (!s_isLast) return;

    // ---- finalize (runs in exactly one block; partials are L2-hot) ----
    __shared__ float G[B_][NSLOT];
    __shared__ float lossS[B_];

    // Each of the 8 warps handles 4 groups; lanes parallelize the 36 slots.
    for (int g = warp; g < B_; g += NWARP) {
        for (int s = lane; s < NSLOT; s += 32) {
            float t = 0.0f;
#pragma unroll
            for (int kb = 0; kb < BPG; kb++) t += g_partials[(g * BPG + kb) * NSLOT + s];
            G[g][s] = t;
        }
    }
    __syncthreads();

    if (threadIdx.x < B_) {
        const int g = threadIdx.x;
        float Gst[4][4], Gsr[4][4], C[4][4];
        int s = 0;
#pragma unroll
        for (int i = 0; i < 4; i++)
#pragma unroll
            for (int j = i; j < 4; j++) { Gst[i][j] = G[g][s]; Gst[j][i] = G[g][s]; s++; }
#pragma unroll
        for (int i = 0; i < 4; i++)
#pragma unroll
            for (int j = i; j < 4; j++) { Gsr[i][j] = G[g][s]; Gsr[j][i] = G[g][s]; s++; }
#pragma unroll
        for (int i = 0; i < 4; i++)
#pragma unroll
            for (int j = 0; j < 4; j++) { C[i][j] = G[g][s]; s++; }

        const float w = wt[g];
        float m1 = kmean4(Gst, Gst, Gst, w);
        float m2 = kmean4(Gsr, Gsr, Gsr, w);
        float m3 = kmean4(Gst, Gsr, C, w);
        lossS[g] = wtout[g] * (m1 + m2 - 2.0f * m3);
    }
    __syncthreads();

    if (threadIdx.x == 0) {
        float t = 0.0f;
#pragma unroll
        for (int g = 0; g < B_; g++) t += lossS[g];
        out[0] = t * (1.0f / (float)B_);
        g_counter = 0;                     // reset for next graph replay
        __threadfence();
    }
}

extern "C" void kernel_launch(void* const* d_in, const int* in_sizes, int n_in,
                              void* d_out, int out_size) {
    const float* f_st  = (const float*)d_in[0];
    const float* f_sr  = (const float*)d_in[1];
    const float* wt    = (const float*)d_in[2];
    const float* wtout = (const float*)d_in[3];
    float* out = (float*)d_out;

    mmd_fused<<<GRID, TPB>>>(f_st, f_sr, wt, wtout, out);
}